// round 1
// baseline (speedup 1.0000x reference)
#include <cuda_runtime.h>
#include <cstdint>
#include <cstddef>

// Problem constants
#define B_   8
#define NU_  1024
#define NI_  2048
#define NT_  3072      // NU_ + NI_
#define D_   64
#define AD_  192       // D_ * (L+1)

// Scratch (device globals; no allocation allowed)
__device__ float g_ego [(size_t)B_*NT_*D_];    // current layer ego embeddings
__device__ float g_side[(size_t)B_*NT_*D_];    // adj @ ego
__device__ float g_alle[(size_t)B_*NT_*AD_];   // concat of ego0|ego1|ego2

// ---------------- packed f32x2 helpers (Blackwell FFMA2 path) ----------------
static __device__ __forceinline__ unsigned long long pk2(float lo, float hi){
    unsigned long long r;
    asm("mov.b64 %0, {%1, %2};" : "=l"(r)
        : "r"(__float_as_uint(lo)), "r"(__float_as_uint(hi)));
    return r;
}
static __device__ __forceinline__ unsigned long long dup2(float v){
    unsigned long long r; unsigned u = __float_as_uint(v);
    asm("mov.b64 %0, {%1, %1};" : "=l"(r) : "r"(u));
    return r;
}
static __device__ __forceinline__ unsigned long long f2fma(unsigned long long a,
                                                           unsigned long long b,
                                                           unsigned long long c){
    unsigned long long d;
    asm("fma.rn.f32x2 %0, %1, %2, %3;" : "=l"(d) : "l"(a), "l"(b), "l"(c));
    return d;
}
static __device__ __forceinline__ float2 upk2(unsigned long long v){
    unsigned lo, hi;
    asm("mov.b64 {%0, %1}, %2;" : "=r"(lo), "=r"(hi) : "l"(v));
    return make_float2(__uint_as_float(lo), __uint_as_float(hi));
}

// ---------------- 1) gather: ego0 = [user_table[u]; item_table[i]] ----------------
__global__ __launch_bounds__(256) void k_gather(const int* __restrict__ u,
                                                const int* __restrict__ it,
                                                const float* __restrict__ utab,
                                                const float* __restrict__ itab){
    int idx = blockIdx.x*256 + threadIdx.x;          // over B*NT*16 float4s
    if (idx >= B_*NT_*16) return;
    int d4 = idx & 15;
    int r  = (idx >> 4) % NT_;
    int b  = idx / (16*NT_);
    float4 v;
    if (r < NU_) v = ((const float4*)(utab + (size_t)u[b*NU_ + r]*D_))[d4];
    else         v = ((const float4*)(itab + (size_t)it[b*NI_ + (r-NU_)]*D_))[d4];
    ((float4*)(g_ego  + ((size_t)b*NT_ + r)*D_ ))[d4] = v;
    ((float4*)(g_alle + ((size_t)b*NT_ + r)*AD_))[d4] = v;   // columns [0,64)
}

// ---------------- 2) side = adj @ ego  ([3072x3072] @ [3072x64]) ----------------
// BM=64 rows x 64 cols tile, BK=16, 128 threads, 8x4 micro-tile, f32x2 FMAs.
__global__ __launch_bounds__(128) void k_side(const float* __restrict__ adj){
    const int b    = blockIdx.y;
    const int row0 = blockIdx.x * 64;
    const float* __restrict__ A = adj   + (size_t)b*NT_*NT_;
    const float* __restrict__ E = g_ego + (size_t)b*NT_*D_;
    __shared__ float As[16][68];   // As[k][row]
    __shared__ float Es[16][68];   // Es[k][col]
    const int tid = threadIdx.x;
    const int ty  = tid >> 4;      // 0..7  -> rows ty*8..ty*8+7
    const int tx  = tid & 15;      // 0..15 -> cols tx*4..tx*4+3
    unsigned long long acc[8][2];
    #pragma unroll
    for (int r=0;r<8;r++){ acc[r][0]=0ull; acc[r][1]=0ull; }

    for (int k0 = 0; k0 < NT_; k0 += 16){
        #pragma unroll
        for (int p=0;p<2;p++){
            int r  = p*32 + (tid>>2);
            int kq = (tid&3)*4;
            float4 v = *(const float4*)(A + (size_t)(row0 + r)*NT_ + k0 + kq);
            As[kq+0][r]=v.x; As[kq+1][r]=v.y; As[kq+2][r]=v.z; As[kq+3][r]=v.w;
        }
        #pragma unroll
        for (int p=0;p<2;p++){
            int kk = p*8 + (tid>>4);
            int c  = (tid&15)*4;
            *(float4*)&Es[kk][c] = *(const float4*)(E + (size_t)(k0+kk)*D_ + c);
        }
        __syncthreads();
        #pragma unroll
        for (int kk=0; kk<16; kk++){
            float4 a0 = *(const float4*)&As[kk][ty*8];
            float4 a1 = *(const float4*)&As[kk][ty*8+4];
            float4 e  = *(const float4*)&Es[kk][tx*4];
            unsigned long long e0 = pk2(e.x, e.y);
            unsigned long long e1 = pk2(e.z, e.w);
            float ar[8] = {a0.x,a0.y,a0.z,a0.w,a1.x,a1.y,a1.z,a1.w};
            #pragma unroll
            for (int r=0;r<8;r++){
                unsigned long long ad = dup2(ar[r]);
                acc[r][0] = f2fma(ad, e0, acc[r][0]);
                acc[r][1] = f2fma(ad, e1, acc[r][1]);
            }
        }
        __syncthreads();
    }
    float* __restrict__ S = g_side + (size_t)b*NT_*D_;
    #pragma unroll
    for (int r=0;r<8;r++){
        int row = row0 + ty*8 + r;
        float2 v0 = upk2(acc[r][0]);
        float2 v1 = upk2(acc[r][1]);
        *(float2*)(S + (size_t)row*D_ + tx*4)     = v0;
        *(float2*)(S + (size_t)row*D_ + tx*4 + 2) = v1;
    }
}

// ---------------- 3) ego' = leaky(side@gcW^T+b) + leaky((ego*side)@biW^T+b) ----------------
__global__ __launch_bounds__(256) void k_xform(const float* __restrict__ gw,
                                               const float* __restrict__ gb,
                                               const float* __restrict__ bw,
                                               const float* __restrict__ bb,
                                               int l){
    const int b  = blockIdx.y;
    const int r0 = blockIdx.x * 16;
    __shared__ float Wg[64][65], Wb[64][65];
    __shared__ float Ss[16][65], Eg[16][65];
    __shared__ float gbias[64], bbias[64];
    const int tid = threadIdx.x;
    for (int i=tid;i<4096;i+=256){ Wg[i>>6][i&63]=gw[i]; Wb[i>>6][i&63]=bw[i]; }
    if (tid<64){ gbias[tid]=gb[tid]; bbias[tid]=bb[tid]; }
    for (int i=tid;i<1024;i+=256){
        int r=i>>6, c=i&63;
        size_t off = ((size_t)b*NT_ + r0 + r)*D_ + c;
        Ss[r][c] = g_side[off];
        Eg[r][c] = g_ego[off];
    }
    __syncthreads();
    const int r  = tid>>4;          // 0..15
    const int c0 = (tid&15)*4;      // 4 output cols per thread
    #pragma unroll
    for (int jj=0;jj<4;jj++){
        int c = c0 + jj;
        float sa = gbias[c], ba = bbias[c];
        #pragma unroll
        for (int k=0;k<64;k++){
            float sv = Ss[r][k];
            sa += sv * Wg[c][k];
            ba += sv * Eg[r][k] * Wb[c][k];
        }
        sa = sa > 0.f ? sa : 0.01f*sa;
        ba = ba > 0.f ? ba : 0.01f*ba;
        float o = sa + ba;
        size_t row = (size_t)b*NT_ + r0 + r;
        g_ego [row*D_  + c] = o;
        g_alle[row*AD_ + (size_t)(l+1)*D_ + c] = o;
    }
}

// ---------------- 4) scores = u_g @ i_g^T  ([1024x192] @ [192x2048]) ----------------
__global__ __launch_bounds__(128) void k_scores(float* __restrict__ out){
    const int b  = blockIdx.z;
    const int m0 = blockIdx.y * 64;
    const int n0 = blockIdx.x * 64;
    const float* __restrict__ U = g_alle + (size_t)b*NT_*AD_;
    const float* __restrict__ V = U + (size_t)NU_*AD_;
    __shared__ float Us[16][68], Is[16][68];
    const int tid = threadIdx.x;
    const int ty  = tid >> 4;      // rows (m)
    const int tx  = tid & 15;      // cols (n)
    unsigned long long acc[8][2];
    #pragma unroll
    for (int r=0;r<8;r++){ acc[r][0]=0ull; acc[r][1]=0ull; }

    for (int k0 = 0; k0 < AD_; k0 += 16){
        #pragma unroll
        for (int p=0;p<2;p++){
            int r  = p*32 + (tid>>2);
            int kq = (tid&3)*4;
            float4 u4 = *(const float4*)(U + (size_t)(m0 + r)*AD_ + k0 + kq);
            Us[kq+0][r]=u4.x; Us[kq+1][r]=u4.y; Us[kq+2][r]=u4.z; Us[kq+3][r]=u4.w;
            float4 i4 = *(const float4*)(V + (size_t)(n0 + r)*AD_ + k0 + kq);
            Is[kq+0][r]=i4.x; Is[kq+1][r]=i4.y; Is[kq+2][r]=i4.z; Is[kq+3][r]=i4.w;
        }
        __syncthreads();
        #pragma unroll
        for (int kk=0; kk<16; kk++){
            float4 a0 = *(const float4*)&Us[kk][ty*8];
            float4 a1 = *(const float4*)&Us[kk][ty*8+4];
            float4 e  = *(const float4*)&Is[kk][tx*4];
            unsigned long long e0 = pk2(e.x, e.y);
            unsigned long long e1 = pk2(e.z, e.w);
            float ar[8] = {a0.x,a0.y,a0.z,a0.w,a1.x,a1.y,a1.z,a1.w};
            #pragma unroll
            for (int r=0;r<8;r++){
                unsigned long long ad = dup2(ar[r]);
                acc[r][0] = f2fma(ad, e0, acc[r][0]);
                acc[r][1] = f2fma(ad, e1, acc[r][1]);
            }
        }
        __syncthreads();
    }
    #pragma unroll
    for (int r=0;r<8;r++){
        int m = m0 + ty*8 + r;
        float2 v0 = upk2(acc[r][0]);
        float2 v1 = upk2(acc[r][1]);
        float* p = out + ((size_t)b*NU_ + m)*NI_ + n0 + tx*4;
        *(float2*)(p)     = v0;
        *(float2*)(p + 2) = v1;
    }
}

// ---------------- 5) in-place row log_softmax over 2048 cols ----------------
__global__ __launch_bounds__(256) void k_lsm(float* __restrict__ out){
    size_t row = blockIdx.x;                 // 0 .. B*NU-1
    float* p = out + row*(size_t)NI_;
    const int tid = threadIdx.x;
    float4* p4 = (float4*)p;
    float4 v0 = p4[tid];
    float4 v1 = p4[tid+256];
    float m = fmaxf(fmaxf(fmaxf(v0.x,v0.y),fmaxf(v0.z,v0.w)),
                    fmaxf(fmaxf(v1.x,v1.y),fmaxf(v1.z,v1.w)));
    #pragma unroll
    for (int o=16;o;o>>=1) m = fmaxf(m, __shfl_xor_sync(0xffffffffu, m, o));
    __shared__ float red[8];
    const int wid = tid>>5, lane = tid&31;
    if (lane==0) red[wid] = m;
    __syncthreads();
    float M = red[0];
    #pragma unroll
    for (int i=1;i<8;i++) M = fmaxf(M, red[i]);
    __syncthreads();
    float s = expf(v0.x-M)+expf(v0.y-M)+expf(v0.z-M)+expf(v0.w-M)
            + expf(v1.x-M)+expf(v1.y-M)+expf(v1.z-M)+expf(v1.w-M);
    #pragma unroll
    for (int o=16;o;o>>=1) s += __shfl_xor_sync(0xffffffffu, s, o);
    if (lane==0) red[wid] = s;
    __syncthreads();
    float S = red[0]+red[1]+red[2]+red[3]+red[4]+red[5]+red[6]+red[7];
    float lse = M + logf(S);
    v0.x -= lse; v0.y -= lse; v0.z -= lse; v0.w -= lse;
    v1.x -= lse; v1.y -= lse; v1.z -= lse; v1.w -= lse;
    p4[tid]     = v0;
    p4[tid+256] = v1;
}

// ---------------- launch ----------------
extern "C" void kernel_launch(void* const* d_in, const int* in_sizes, int n_in,
                              void* d_out, int out_size){
    const int*   u_idx = (const int*)  d_in[0];
    const int*   i_idx = (const int*)  d_in[1];
    const float* adj   = (const float*)d_in[2];
    const float* utab  = (const float*)d_in[3];
    const float* itab  = (const float*)d_in[4];
    const float* gw    = (const float*)d_in[5];
    const float* gb    = (const float*)d_in[6];
    const float* bw    = (const float*)d_in[7];
    const float* bb    = (const float*)d_in[8];
    float* out = (float*)d_out;

    k_gather<<<(B_*NT_*16 + 255)/256, 256>>>(u_idx, i_idx, utab, itab);
    for (int l = 0; l < 2; l++){
        k_side <<<dim3(NT_/64, B_), 128>>>(adj);
        k_xform<<<dim3(NT_/16, B_), 256>>>(gw + (size_t)l*D_*D_, gb + l*D_,
                                           bw + (size_t)l*D_*D_, bb + l*D_, l);
    }
    k_scores<<<dim3(NI_/64, NU_/64, B_), 128>>>(out);
    k_lsm   <<<B_*NU_, 256>>>(out);
}

// round 3
// speedup vs baseline: 1.4404x; 1.4404x over previous
#include <cuda_runtime.h>
#include <cuda_bf16.h>
#include <cstdint>
#include <cstddef>

#define B_   8
#define NU_  1024
#define NI_  2048
#define NT_  3072
#define D_   64
#define AD_  192

// ---- device scratch ----
__device__ float g_ego [(size_t)B_*NT_*D_];
__device__ float g_side[(size_t)B_*NT_*D_];
__device__ unsigned short g_alleh[(size_t)B_*NT_*AD_];  // bf16 hi of all-embs [b][row][192]
__device__ unsigned short g_allel[(size_t)B_*NT_*AD_];  // bf16 lo
__device__ unsigned short g_egoTh[(size_t)B_*D_*NT_];   // ego^T bf16 hi [b][n][k]
__device__ unsigned short g_egoTl[(size_t)B_*D_*NT_];   // bf16 lo

// ---- helpers ----
static __device__ __forceinline__ uint32_t smem_u32(const void* p){
    uint32_t a;
    asm("{ .reg .u64 t; cvta.to.shared.u64 t, %1; cvt.u32.u64 %0, t; }" : "=r"(a) : "l"(p));
    return a;
}
// split fp32 pair -> packed bf16x2 hi + lo (e0 -> low half, e1 -> high half)
static __device__ __forceinline__ void split2(float e0, float e1, uint32_t& h, uint32_t& l){
    asm("cvt.rn.bf16x2.f32 %0, %1, %2;" : "=r"(h) : "f"(e1), "f"(e0));
    float h0 = __uint_as_float(h << 16);
    float h1 = __uint_as_float(h & 0xffff0000u);
    float l0 = e0 - h0, l1 = e1 - h1;
    asm("cvt.rn.bf16x2.f32 %0, %1, %2;" : "=r"(l) : "f"(l1), "f"(l0));
}
static __device__ __forceinline__ void ldsm4(uint32_t* r, uint32_t addr){
    asm volatile("ldmatrix.sync.aligned.m8n8.x4.shared.b16 {%0,%1,%2,%3}, [%4];"
        : "=r"(r[0]), "=r"(r[1]), "=r"(r[2]), "=r"(r[3]) : "r"(addr));
}
static __device__ __forceinline__ void mma16816(float* c, const uint32_t* a,
                                                uint32_t b0, uint32_t b1){
    asm volatile("mma.sync.aligned.m16n8k16.row.col.f32.bf16.bf16.f32 "
        "{%0,%1,%2,%3}, {%4,%5,%6,%7}, {%8,%9}, {%0,%1,%2,%3};"
        : "+f"(c[0]), "+f"(c[1]), "+f"(c[2]), "+f"(c[3])
        : "r"(a[0]), "r"(a[1]), "r"(a[2]), "r"(a[3]), "r"(b0), "r"(b1));
}
static __device__ __forceinline__ void stv4(uint32_t addr, uint32_t x, uint32_t y,
                                            uint32_t z, uint32_t w){
    asm volatile("st.shared.v4.b32 [%0], {%1,%2,%3,%4};" :: "r"(addr),
                 "r"(x), "r"(y), "r"(z), "r"(w) : "memory");
}

// SMEM layout (per stage, bf16 elements, row stride 40 elems = 80B):
//  Ah: 64x32 @ +0 (5120B)  Al: +5120  Bh: +10240  Bl: +15360 ; stage = 20480B
#define ST_   20480u
#define SMEM_MMA (2*ST_)

// ---------------- 1) gather: ego0 + alle[:,0:64] ----------------
__global__ __launch_bounds__(256) void k_gather(const int* __restrict__ u,
                                                const int* __restrict__ it,
                                                const float* __restrict__ utab,
                                                const float* __restrict__ itab){
    int idx = blockIdx.x*256 + threadIdx.x;          // over B*NT*16 float4s
    if (idx >= B_*NT_*16) return;
    int d4 = idx & 15;
    int r  = (idx >> 4) % NT_;
    int b  = idx / (16*NT_);
    float4 v;
    if (r < NU_) v = ((const float4*)(utab + (size_t)u[b*NU_ + r]*D_))[d4];
    else         v = ((const float4*)(itab + (size_t)it[b*NI_ + (r-NU_)]*D_))[d4];
    ((float4*)(g_ego + ((size_t)b*NT_ + r)*D_))[d4] = v;
    uint32_t h0,l0,h1,l1;
    split2(v.x, v.y, h0, l0);
    split2(v.z, v.w, h1, l1);
    size_t ao = ((size_t)b*NT_ + r)*AD_ + d4*4;
    *(uint2*)(g_alleh + ao) = make_uint2(h0, h1);
    *(uint2*)(g_allel + ao) = make_uint2(l0, l1);
}

// ---------------- 2) transpose + split ego -> egoT hi/lo ----------------
__global__ __launch_bounds__(256) void k_egoT(){
    const int b  = blockIdx.y;
    const int k0 = blockIdx.x * 32;
    __shared__ float t[32][65];
    const int tid = threadIdx.x;
    #pragma unroll
    for (int i=0;i<8;i++){
        int e = i*256 + tid;
        int k = e >> 6, n = e & 63;
        t[k][n] = g_ego[((size_t)b*NT_ + k0 + k)*D_ + n];
    }
    __syncthreads();
    const int n  = tid >> 2;
    const int kq = (tid & 3) * 8;
    uint32_t hh[4], ll[4];
    #pragma unroll
    for (int j=0;j<4;j++)
        split2(t[kq+2*j][n], t[kq+2*j+1][n], hh[j], ll[j]);
    size_t o = ((size_t)b*D_ + n)*NT_ + k0 + kq;
    *(uint4*)(g_egoTh + o) = make_uint4(hh[0],hh[1],hh[2],hh[3]);
    *(uint4*)(g_egoTl + o) = make_uint4(ll[0],ll[1],ll[2],ll[3]);
}

// ---------------- 3) side = adj @ ego via mma.sync bf16-split ----------------
// BM=64, BN=64(=D), BK=32, 128 threads (4 warps, 16 rows each), 96 chunks.
__global__ __launch_bounds__(128) void k_side_mma(const float* __restrict__ adj){
    extern __shared__ char smem[];
    const uint32_t sb = smem_u32(smem);
    const int tid = threadIdx.x, lane = tid & 31, wid = tid >> 5;
    const int b = blockIdx.y, row0 = blockIdx.x * 64;
    const float* __restrict__ A = adj + (size_t)b*NT_*NT_;
    const unsigned short* __restrict__ BhG = g_egoTh + (size_t)b*D_*NT_;
    const unsigned short* __restrict__ BlG = g_egoTl + (size_t)b*D_*NT_;

    float acc[8][4];
    #pragma unroll
    for (int i=0;i<8;i++){ acc[i][0]=0.f; acc[i][1]=0.f; acc[i][2]=0.f; acc[i][3]=0.f; }

    const int ar = tid >> 1;            // 0..63 : A row / B n-row
    const int ak = (tid & 1) * 16;      // k offset within chunk
    float4 pa[4];                       // 16 fp32 of adj
    uint4 pbh[2], pbl[2];               // 16 bf16 hi + lo of egoT

    // ldmatrix base addresses (per warp / lane)
    const int m0 = wid * 16;
    const uint32_t aoff = (uint32_t)((m0 + (lane & 15))*40 + ((lane >> 4) & 1)*8) * 2;
    const uint32_t boff = (uint32_t)((((lane >> 4) & 1)*8 + (lane & 7))*40 + ((lane >> 3) & 1)*8) * 2;
    const uint32_t soff = (uint32_t)(ar*40 + ak) * 2;

#define LOADC(c) { \
    const float4* s4 = (const float4*)(A + (size_t)(row0+ar)*NT_ + (c)*32 + ak); \
    pa[0]=s4[0]; pa[1]=s4[1]; pa[2]=s4[2]; pa[3]=s4[3]; \
    const uint4* bh4 = (const uint4*)(BhG + (size_t)ar*NT_ + (c)*32 + ak); \
    pbh[0]=bh4[0]; pbh[1]=bh4[1]; \
    const uint4* bl4 = (const uint4*)(BlG + (size_t)ar*NT_ + (c)*32 + ak); \
    pbl[0]=bl4[0]; pbl[1]=bl4[1]; }

#define STOREC(s) { \
    uint32_t h[8], l[8]; \
    split2(pa[0].x, pa[0].y, h[0], l[0]); split2(pa[0].z, pa[0].w, h[1], l[1]); \
    split2(pa[1].x, pa[1].y, h[2], l[2]); split2(pa[1].z, pa[1].w, h[3], l[3]); \
    split2(pa[2].x, pa[2].y, h[4], l[4]); split2(pa[2].z, pa[2].w, h[5], l[5]); \
    split2(pa[3].x, pa[3].y, h[6], l[6]); split2(pa[3].z, pa[3].w, h[7], l[7]); \
    uint32_t base = sb + (s)*ST_ + soff; \
    stv4(base,        h[0],h[1],h[2],h[3]); stv4(base+16,       h[4],h[5],h[6],h[7]); \
    stv4(base+5120,   l[0],l[1],l[2],l[3]); stv4(base+5120+16,  l[4],l[5],l[6],l[7]); \
    stv4(base+10240,  pbh[0].x,pbh[0].y,pbh[0].z,pbh[0].w); \
    stv4(base+10240+16, pbh[1].x,pbh[1].y,pbh[1].z,pbh[1].w); \
    stv4(base+15360,  pbl[0].x,pbl[0].y,pbl[0].z,pbl[0].w); \
    stv4(base+15360+16, pbl[1].x,pbl[1].y,pbl[1].z,pbl[1].w); }

#define COMPUTE(s) { \
    uint32_t abase_h = sb + (s)*ST_ + aoff; \
    uint32_t abase_l = abase_h + 5120; \
    uint32_t bbase_h = sb + (s)*ST_ + 10240 + boff; \
    uint32_t bbase_l = bbase_h + 5120; \
    _Pragma("unroll") \
    for (int ks = 0; ks < 2; ks++){ \
        uint32_t ah[4], al[4]; \
        ldsm4(ah, abase_h + ks*32); \
        ldsm4(al, abase_l + ks*32); \
        _Pragma("unroll") \
        for (int nt2 = 0; nt2 < 4; nt2++){ \
            uint32_t rh[4], rl[4]; \
            ldsm4(rh, bbase_h + nt2*1280 + ks*32); \
            ldsm4(rl, bbase_l + nt2*1280 + ks*32); \
            mma16816(acc[2*nt2],   ah, rh[0], rh[1]); \
            mma16816(acc[2*nt2],   ah, rl[0], rl[1]); \
            mma16816(acc[2*nt2],   al, rh[0], rh[1]); \
            mma16816(acc[2*nt2+1], ah, rh[2], rh[3]); \
            mma16816(acc[2*nt2+1], ah, rl[2], rl[3]); \
            mma16816(acc[2*nt2+1], al, rh[2], rh[3]); \
        } \
    } }

    LOADC(0); STOREC(0); __syncthreads();
    for (int c = 0; c < 96; c++){
        const int s = c & 1;
        if (c < 95) LOADC(c+1);
        COMPUTE(s);
        if (c < 95) STOREC(s^1);
        __syncthreads();
    }
#undef LOADC
#undef STOREC

    // epilogue
    const int r = lane >> 2, cq = (lane & 3)*2;
    float* S = g_side + ((size_t)b*NT_ + row0 + m0)*D_;
    #pragma unroll
    for (int nt = 0; nt < 8; nt++){
        *(float2*)(S + (size_t)r*D_     + nt*8 + cq) = make_float2(acc[nt][0], acc[nt][1]);
        *(float2*)(S + (size_t)(r+8)*D_ + nt*8 + cq) = make_float2(acc[nt][2], acc[nt][3]);
    }
}

// ---------------- 4) ego' transform ----------------
__global__ __launch_bounds__(256) void k_xform(const float* __restrict__ gw,
                                               const float* __restrict__ gb,
                                               const float* __restrict__ bw,
                                               const float* __restrict__ bb,
                                               int l){
    const int b  = blockIdx.y;
    const int r0 = blockIdx.x * 16;
    __shared__ float Wg[64][65], Wb[64][65];
    __shared__ float Ss[16][65], Eg[16][65];
    __shared__ float gbias[64], bbias[64];
    const int tid = threadIdx.x;
    for (int i=tid;i<4096;i+=256){ Wg[i>>6][i&63]=gw[i]; Wb[i>>6][i&63]=bw[i]; }
    if (tid<64){ gbias[tid]=gb[tid]; bbias[tid]=bb[tid]; }
    for (int i=tid;i<1024;i+=256){
        int r=i>>6, c=i&63;
        size_t off = ((size_t)b*NT_ + r0 + r)*D_ + c;
        Ss[r][c] = g_side[off];
        Eg[r][c] = g_ego[off];
    }
    __syncthreads();
    const int r  = tid>>4;
    const int c0 = (tid&15)*4;
    float o[4];
    #pragma unroll
    for (int jj=0;jj<4;jj++){
        int c = c0 + jj;
        float sa = gbias[c], ba = bbias[c];
        #pragma unroll
        for (int k=0;k<64;k++){
            float sv = Ss[r][k];
            sa += sv * Wg[c][k];
            ba += sv * Eg[r][k] * Wb[c][k];
        }
        sa = sa > 0.f ? sa : 0.01f*sa;
        ba = ba > 0.f ? ba : 0.01f*ba;
        o[jj] = sa + ba;
    }
    size_t row = (size_t)b*NT_ + r0 + r;
    *(float4*)(g_ego + row*D_ + c0) = make_float4(o[0],o[1],o[2],o[3]);
    uint32_t ha,la,hb2,lb2;
    split2(o[0], o[1], ha, la);
    split2(o[2], o[3], hb2, lb2);
    size_t ao = row*AD_ + (size_t)(l+1)*D_ + c0;
    *(uint2*)(g_alleh + ao) = make_uint2(ha, hb2);
    *(uint2*)(g_allel + ao) = make_uint2(la, lb2);
}

// ---------------- 5) scores = u_g @ i_g^T via mma.sync bf16-split ----------------
// BM=64, BN=64, BK=32, K=192 (6 chunks), operands pre-split.
__global__ __launch_bounds__(128) void k_scores_mma(float* __restrict__ out){
    extern __shared__ char smem[];
    const uint32_t sb = smem_u32(smem);
    const int tid = threadIdx.x, lane = tid & 31, wid = tid >> 5;
    const int b  = blockIdx.z;
    const int mB = blockIdx.y * 64;
    const int n0 = blockIdx.x * 64;
    const unsigned short* __restrict__ AhG = g_alleh + ((size_t)b*NT_ + mB)*AD_;
    const unsigned short* __restrict__ AlG = g_allel + ((size_t)b*NT_ + mB)*AD_;
    const unsigned short* __restrict__ IhG = g_alleh + ((size_t)b*NT_ + NU_ + n0)*AD_;
    const unsigned short* __restrict__ IlG = g_allel + ((size_t)b*NT_ + NU_ + n0)*AD_;

    float acc[8][4];
    #pragma unroll
    for (int i=0;i<8;i++){ acc[i][0]=0.f; acc[i][1]=0.f; acc[i][2]=0.f; acc[i][3]=0.f; }

    const int ar = tid >> 1;
    const int ak = (tid & 1) * 16;
    uint4 pah[2], pal[2], pbh[2], pbl[2];

    const int m0 = wid * 16;
    const uint32_t aoff = (uint32_t)((m0 + (lane & 15))*40 + ((lane >> 4) & 1)*8) * 2;
    const uint32_t boff = (uint32_t)((((lane >> 4) & 1)*8 + (lane & 7))*40 + ((lane >> 3) & 1)*8) * 2;
    const uint32_t soff = (uint32_t)(ar*40 + ak) * 2;

#define LOADS(c) { \
    const uint4* p; \
    p = (const uint4*)(AhG + (size_t)ar*AD_ + (c)*32 + ak); pah[0]=p[0]; pah[1]=p[1]; \
    p = (const uint4*)(AlG + (size_t)ar*AD_ + (c)*32 + ak); pal[0]=p[0]; pal[1]=p[1]; \
    p = (const uint4*)(IhG + (size_t)ar*AD_ + (c)*32 + ak); pbh[0]=p[0]; pbh[1]=p[1]; \
    p = (const uint4*)(IlG + (size_t)ar*AD_ + (c)*32 + ak); pbl[0]=p[0]; pbl[1]=p[1]; }

#define STORES(s) { \
    uint32_t base = sb + (s)*ST_ + soff; \
    stv4(base,          pah[0].x,pah[0].y,pah[0].z,pah[0].w); \
    stv4(base+16,       pah[1].x,pah[1].y,pah[1].z,pah[1].w); \
    stv4(base+5120,     pal[0].x,pal[0].y,pal[0].z,pal[0].w); \
    stv4(base+5120+16,  pal[1].x,pal[1].y,pal[1].z,pal[1].w); \
    stv4(base+10240,    pbh[0].x,pbh[0].y,pbh[0].z,pbh[0].w); \
    stv4(base+10240+16, pbh[1].x,pbh[1].y,pbh[1].z,pbh[1].w); \
    stv4(base+15360,    pbl[0].x,pbl[0].y,pbl[0].z,pbl[0].w); \
    stv4(base+15360+16, pbl[1].x,pbl[1].y,pbl[1].z,pbl[1].w); }

    LOADS(0); STORES(0); __syncthreads();
    for (int c = 0; c < 6; c++){
        const int s = c & 1;
        if (c < 5) LOADS(c+1);
        COMPUTE(s);
        if (c < 5) STORES(s^1);
        __syncthreads();
    }
#undef LOADS
#undef STORES

    const int r = lane >> 2, cq = (lane & 3)*2;
    float* O = out + ((size_t)b*NU_ + mB + m0)*NI_ + n0;
    #pragma unroll
    for (int nt = 0; nt < 8; nt++){
        *(float2*)(O + (size_t)r*NI_     + nt*8 + cq) = make_float2(acc[nt][0], acc[nt][1]);
        *(float2*)(O + (size_t)(r+8)*NI_ + nt*8 + cq) = make_float2(acc[nt][2], acc[nt][3]);
    }
}

// ---------------- 6) in-place row log_softmax over 2048 cols ----------------
__global__ __launch_bounds__(256) void k_lsm(float* __restrict__ out){
    size_t row = blockIdx.x;
    float* p = out + row*(size_t)NI_;
    const int tid = threadIdx.x;
    float4* p4 = (float4*)p;
    float4 v0 = p4[tid];
    float4 v1 = p4[tid+256];
    float m = fmaxf(fmaxf(fmaxf(v0.x,v0.y),fmaxf(v0.z,v0.w)),
                    fmaxf(fmaxf(v1.x,v1.y),fmaxf(v1.z,v1.w)));
    #pragma unroll
    for (int o=16;o;o>>=1) m = fmaxf(m, __shfl_xor_sync(0xffffffffu, m, o));
    __shared__ float red[8];
    const int wid = tid>>5, lane = tid&31;
    if (lane==0) red[wid] = m;
    __syncthreads();
    float M = red[0];
    #pragma unroll
    for (int i=1;i<8;i++) M = fmaxf(M, red[i]);
    __syncthreads();
    float s = expf(v0.x-M)+expf(v0.y-M)+expf(v0.z-M)+expf(v0.w-M)
            + expf(v1.x-M)+expf(v1.y-M)+expf(v1.z-M)+expf(v1.w-M);
    #pragma unroll
    for (int o=16;o;o>>=1) s += __shfl_xor_sync(0xffffffffu, s, o);
    if (lane==0) red[wid] = s;
    __syncthreads();
    float S = red[0]+red[1]+red[2]+red[3]+red[4]+red[5]+red[6]+red[7];
    float lse = M + logf(S);
    v0.x -= lse; v0.y -= lse; v0.z -= lse; v0.w -= lse;
    v1.x -= lse; v1.y -= lse; v1.z -= lse; v1.w -= lse;
    p4[tid]     = v0;
    p4[tid+256] = v1;
}

// ---------------- launch ----------------
extern "C" void kernel_launch(void* const* d_in, const int* in_sizes, int n_in,
                              void* d_out, int out_size){
    const int*   u_idx = (const int*)  d_in[0];
    const int*   i_idx = (const int*)  d_in[1];
    const float* adj   = (const float*)d_in[2];
    const float* utab  = (const float*)d_in[3];
    const float* itab  = (const float*)d_in[4];
    const float* gw    = (const float*)d_in[5];
    const float* gb    = (const float*)d_in[6];
    const float* bw    = (const float*)d_in[7];
    const float* bb    = (const float*)d_in[8];
    float* out = (float*)d_out;

    k_gather<<<(B_*NT_*16 + 255)/256, 256>>>(u_idx, i_idx, utab, itab);
    for (int l = 0; l < 2; l++){
        k_egoT    <<<dim3(NT_/32, B_), 256>>>();
        k_side_mma<<<dim3(NT_/64, B_), 128, SMEM_MMA>>>(adj);
        k_xform   <<<dim3(NT_/16, B_), 256>>>(gw + (size_t)l*D_*D_, gb + l*D_,
                                              bw + (size_t)l*D_*D_, bb + l*D_, l);
    }
    k_scores_mma<<<dim3(NI_/64, NU_/64, B_), 128, SMEM_MMA>>>(out);
    k_lsm       <<<B_*NU_, 256>>>(out);
}